// round 1
// baseline (speedup 1.0000x reference)
#include <cuda_runtime.h>
#include <cuda_bf16.h>

// Skinning: out[b,v,i] = sum_j w[v,j] * (M[b,j,i,0]*x + M[b,j,i,1]*y + M[b,j,i,2]*z + M[b,j,i,3])
// vertices:  [1, V, 3]  float32   (d_in[0], size 3V)
// weights:   [1, V, J]  float32   (d_in[1], size V*J), J = 52
// M:         [B, J, 4, 4] float32 (d_in[2], size B*J*16)
// out:       [B, V, 3]  float32

#define J_JOINTS 52
#define TPB      256
#define BCHUNK   8

__global__ __launch_bounds__(TPB, 3)
void skinning_kernel(const float* __restrict__ verts,
                     const float* __restrict__ weights,
                     const float* __restrict__ xf,
                     float* __restrict__ out,
                     int V, int B)
{
    // Shared: rows 0..2 of each 4x4 transform for this batch chunk.
    // sM[bb][j][r] = float4(M[b0+bb, j, r, 0..3])
    __shared__ float4 sM[BCHUNK][J_JOINTS][3];

    const int b0 = blockIdx.y * BCHUNK;

    // Cooperative load of the transform chunk: BCHUNK*J*3 float4s.
    const int nElems = BCHUNK * J_JOINTS * 3;
    for (int i = threadIdx.x; i < nElems; i += TPB) {
        int bb  = i / (J_JOINTS * 3);
        int rem = i - bb * (J_JOINTS * 3);
        int jj  = rem / 3;
        int r   = rem - jj * 3;
        int b   = b0 + bb;
        float4 val = make_float4(0.f, 0.f, 0.f, 0.f);
        if (b < B) {
            val = *reinterpret_cast<const float4*>(
                &xf[((size_t)b * J_JOINTS + jj) * 16 + r * 4]);
        }
        sM[bb][jj][r] = val;
    }
    __syncthreads();

    const int v = blockIdx.x * TPB + threadIdx.x;
    if (v >= V) return;

    const float x = verts[v * 3 + 0];
    const float y = verts[v * 3 + 1];
    const float z = verts[v * 3 + 2];

    // Load all 52 weights into registers via 13 float4 loads.
    // Row offset v*52 floats = v*208 bytes -> 16B aligned.
    float wt[J_JOINTS];
    {
        const float4* wrow = reinterpret_cast<const float4*>(weights + (size_t)v * J_JOINTS);
#pragma unroll
        for (int q = 0; q < J_JOINTS / 4; q++) {
            float4 t = wrow[q];
            wt[q * 4 + 0] = t.x;
            wt[q * 4 + 1] = t.y;
            wt[q * 4 + 2] = t.z;
            wt[q * 4 + 3] = t.w;
        }
    }

#pragma unroll 1
    for (int bb = 0; bb < BCHUNK; bb++) {
        const int b = b0 + bb;
        if (b >= B) break;

        float a0 = 0.f, a1 = 0.f, a2 = 0.f;
#pragma unroll
        for (int j = 0; j < J_JOINTS; j++) {
            const float wj = wt[j];
            const float4 m0 = sM[bb][j][0];
            const float4 m1 = sM[bb][j][1];
            const float4 m2 = sM[bb][j][2];
            float r0 = fmaf(m0.x, x, fmaf(m0.y, y, fmaf(m0.z, z, m0.w)));
            float r1 = fmaf(m1.x, x, fmaf(m1.y, y, fmaf(m1.z, z, m1.w)));
            float r2 = fmaf(m2.x, x, fmaf(m2.y, y, fmaf(m2.z, z, m2.w)));
            a0 = fmaf(wj, r0, a0);
            a1 = fmaf(wj, r1, a1);
            a2 = fmaf(wj, r2, a2);
        }

        float* o = out + ((size_t)b * V + v) * 3;
        o[0] = a0;
        o[1] = a1;
        o[2] = a2;
    }
}

extern "C" void kernel_launch(void* const* d_in, const int* in_sizes, int n_in,
                              void* d_out, int out_size)
{
    const float* verts   = (const float*)d_in[0];
    const float* weights = (const float*)d_in[1];
    const float* xf      = (const float*)d_in[2];
    float*       out     = (float*)d_out;

    const int V = in_sizes[0] / 3;
    const int B = in_sizes[2] / (J_JOINTS * 16);

    dim3 grid((V + TPB - 1) / TPB, (B + BCHUNK - 1) / BCHUNK);
    skinning_kernel<<<grid, TPB>>>(verts, weights, xf, out, V, B);
}

// round 2
// speedup vs baseline: 1.0365x; 1.0365x over previous
#include <cuda_runtime.h>
#include <cuda_bf16.h>

// Skinning: out[b,v,i] = sum_j w[v,j] * (M[b,j,i,:] . [x,y,z,1])
// vertices:  [1, V, 3]   float32 (d_in[0])
// weights:   [1, V, J]   float32 (d_in[1]), J = 52
// M:         [B, J, 4, 4] float32 (d_in[2])
// out:       [B, V, 3]   float32
//
// R2: 2 vertices per thread. Matrix smem-broadcast traffic (the R1 bottleneck,
// L1=84.5%) is amortized over 2 vertices -> L1 and FMA balanced at ~12 cyc
// per warp-(bb,j) iteration.

#define J_JOINTS 52
#define TPB      128
#define BCHUNK   8

__global__ __launch_bounds__(TPB, 3)
void skinning_kernel(const float* __restrict__ verts,
                     const float* __restrict__ weights,
                     const float* __restrict__ xf,
                     float* __restrict__ out,
                     int V, int B)
{
    // Rows 0..2 of each 4x4 transform for this batch chunk.
    __shared__ float4 sM[BCHUNK][J_JOINTS][3];

    const int b0 = blockIdx.y * BCHUNK;

    const int nElems = BCHUNK * J_JOINTS * 3;
    for (int i = threadIdx.x; i < nElems; i += TPB) {
        int bb  = i / (J_JOINTS * 3);
        int rem = i - bb * (J_JOINTS * 3);
        int jj  = rem / 3;
        int r   = rem - jj * 3;
        int b   = b0 + bb;
        float4 val = make_float4(0.f, 0.f, 0.f, 0.f);
        if (b < B) {
            val = *reinterpret_cast<const float4*>(
                &xf[((size_t)b * J_JOINTS + jj) * 16 + r * 4]);
        }
        sM[bb][jj][r] = val;
    }
    __syncthreads();

    const int pair = blockIdx.x * TPB + threadIdx.x;
    const int v0 = pair * 2;
    if (v0 >= V) return;
    const bool has2 = (v0 + 1 < V);
    const int v1 = has2 ? (v0 + 1) : v0;

    // Vertex coords for both vertices.
    const float xa = verts[v0 * 3 + 0];
    const float ya = verts[v0 * 3 + 1];
    const float za = verts[v0 * 3 + 2];
    const float xb = verts[v1 * 3 + 0];
    const float yb = verts[v1 * 3 + 1];
    const float zb = verts[v1 * 3 + 2];

    // Weights for both vertices: 2 x 13 float4 loads (row stride 208 B, 16B aligned).
    float wa[J_JOINTS], wb[J_JOINTS];
    {
        const float4* ra = reinterpret_cast<const float4*>(weights + (size_t)v0 * J_JOINTS);
        const float4* rb = reinterpret_cast<const float4*>(weights + (size_t)v1 * J_JOINTS);
#pragma unroll
        for (int q = 0; q < J_JOINTS / 4; q++) {
            float4 ta = ra[q];
            wa[q * 4 + 0] = ta.x; wa[q * 4 + 1] = ta.y;
            wa[q * 4 + 2] = ta.z; wa[q * 4 + 3] = ta.w;
            float4 tb = rb[q];
            wb[q * 4 + 0] = tb.x; wb[q * 4 + 1] = tb.y;
            wb[q * 4 + 2] = tb.z; wb[q * 4 + 3] = tb.w;
        }
    }

#pragma unroll 1
    for (int bb = 0; bb < BCHUNK; bb++) {
        const int b = b0 + bb;
        if (b >= B) break;

        float a0 = 0.f, a1 = 0.f, a2 = 0.f;   // vertex A accumulators
        float c0 = 0.f, c1 = 0.f, c2 = 0.f;   // vertex B accumulators

#pragma unroll 4
        for (int j = 0; j < J_JOINTS; j++) {
            const float4 m0 = sM[bb][j][0];
            const float4 m1 = sM[bb][j][1];
            const float4 m2 = sM[bb][j][2];

            const float wja = wa[j];
            const float wjb = wb[j];

            float r0a = fmaf(m0.x, xa, fmaf(m0.y, ya, fmaf(m0.z, za, m0.w)));
            float r1a = fmaf(m1.x, xa, fmaf(m1.y, ya, fmaf(m1.z, za, m1.w)));
            float r2a = fmaf(m2.x, xa, fmaf(m2.y, ya, fmaf(m2.z, za, m2.w)));
            a0 = fmaf(wja, r0a, a0);
            a1 = fmaf(wja, r1a, a1);
            a2 = fmaf(wja, r2a, a2);

            float r0b = fmaf(m0.x, xb, fmaf(m0.y, yb, fmaf(m0.z, zb, m0.w)));
            float r1b = fmaf(m1.x, xb, fmaf(m1.y, yb, fmaf(m1.z, zb, m1.w)));
            float r2b = fmaf(m2.x, xb, fmaf(m2.y, yb, fmaf(m2.z, zb, m2.w)));
            c0 = fmaf(wjb, r0b, c0);
            c1 = fmaf(wjb, r1b, c1);
            c2 = fmaf(wjb, r2b, c2);
        }

        // 2 adjacent vertices -> 24 contiguous bytes, 8B-aligned -> 3x float2.
        float* o = out + ((size_t)b * V + v0) * 3;
        if (has2) {
            float2* o2 = reinterpret_cast<float2*>(o);
            o2[0] = make_float2(a0, a1);
            o2[1] = make_float2(a2, c0);
            o2[2] = make_float2(c1, c2);
        } else {
            o[0] = a0; o[1] = a1; o[2] = a2;
        }
    }
}

extern "C" void kernel_launch(void* const* d_in, const int* in_sizes, int n_in,
                              void* d_out, int out_size)
{
    const float* verts   = (const float*)d_in[0];
    const float* weights = (const float*)d_in[1];
    const float* xf      = (const float*)d_in[2];
    float*       out     = (float*)d_out;

    const int V = in_sizes[0] / 3;
    const int B = in_sizes[2] / (J_JOINTS * 16);

    const int pairs = (V + 1) / 2;
    dim3 grid((pairs + TPB - 1) / TPB, (B + BCHUNK - 1) / BCHUNK);
    skinning_kernel<<<grid, TPB>>>(verts, weights, xf, out, V, B);
}

// round 3
// speedup vs baseline: 1.1943x; 1.1522x over previous
#include <cuda_runtime.h>
#include <cuda_bf16.h>

// Skinning: out[b,v,i] = sum_j w[v,j] * (M[b,j,i,:] . [x,y,z,1])
// vertices:  [1, V, 3]    float32 (d_in[0])
// weights:   [1, V, J]    float32 (d_in[1]), J = 52
// M:         [B, J, 4, 4] float32 (d_in[2])
// out:       [B, V, 3]    float32
//
// R3: packed fma.rn.f32x2 over batch pairs (halves FFMA warp-instrs, the R1/R2
// binding floor), 4 vertices per thread (amortize smem broadcast), and a
// weight-transpose pre-pass so weights stream via 1 coalesced LDG.128 per j
// instead of occupying 104 registers.

#define J_JOINTS 52
#define TPB      128
#define BCHUNK   8            // batches per block (4 batch-pairs)
#define VPT      4            // vertices per thread
#define MAXV     100000

typedef unsigned long long u64;

// Transposed weights scratch: wT[j*V + v]
__device__ float g_wT[J_JOINTS * MAXV];

__device__ __forceinline__ u64 pack2(float a, float b) {
    u64 r;
    asm("mov.b64 %0, {%1, %2};" : "=l"(r) : "f"(a), "f"(b));
    return r;
}
__device__ __forceinline__ void unpack2(u64 v, float& a, float& b) {
    asm("mov.b64 {%0, %1}, %2;" : "=f"(a), "=f"(b) : "l"(v));
}
__device__ __forceinline__ u64 ffma2(u64 a, u64 b, u64 c) {
    u64 d;
    asm("fma.rn.f32x2 %0, %1, %2, %3;" : "=l"(d) : "l"(a), "l"(b), "l"(c));
    return d;
}

// ---------------- weight transpose: W[v][j] -> wT[j][v] ----------------
#define TR_VERTS 64
__global__ void transpose_w_kernel(const float* __restrict__ w, int V)
{
    __shared__ float sm[TR_VERTS * 53];   // padded stride 53 to dodge conflicts
    const int v0 = blockIdx.x * TR_VERTS;
    const int nv = min(TR_VERTS, V - v0);
    const int total = nv * J_JOINTS;

    // coalesced linear read of the W tile
    for (int idx = threadIdx.x; idx < total; idx += blockDim.x) {
        int i = idx / J_JOINTS;
        int j = idx - i * J_JOINTS;
        sm[i * 53 + j] = w[(size_t)(v0 + i) * J_JOINTS + j];
    }
    __syncthreads();

    // coalesced write: consecutive threads -> consecutive v
    for (int idx = threadIdx.x; idx < J_JOINTS * nv; idx += blockDim.x) {
        int j = idx / nv;
        int i = idx - j * nv;
        g_wT[(size_t)j * V + v0 + i] = sm[i * 53 + j];
    }
}

// ---------------- main skinning kernel ----------------
__global__ __launch_bounds__(TPB, 4)
void skinning_kernel(const float* __restrict__ verts,
                     const float* __restrict__ xf,
                     float* __restrict__ out,
                     int V, int B)
{
    // sM[bp][j][q]: q in 0..5 covers rows 0..2, each row = 2 double2.
    // Each double2 = 2 x f32x2; f32x2 = (M[b0+2bp], M[b0+2bp+1]) for one (r,c).
    __shared__ double2 sM[BCHUNK / 2][J_JOINTS][6];

    const int b0 = blockIdx.y * BCHUNK;

    // Cooperative fill with batch-pair interleave.
    const int nElems = (BCHUNK / 2) * J_JOINTS * 6;   // 1248
    for (int i = threadIdx.x; i < nElems; i += TPB) {
        int bp  = i / (J_JOINTS * 6);
        int rem = i - bp * (J_JOINTS * 6);
        int j   = rem / 6;
        int q   = rem - j * 6;
        int r   = q >> 1;          // row 0..2
        int c2  = q & 1;           // component pair 0 -> (c0,c1), 1 -> (c2,c3)
        int ba  = b0 + 2 * bp;
        int bb2 = ba + 1;

        float2 ma = make_float2(0.f, 0.f), mb = make_float2(0.f, 0.f);
        if (ba < B)
            ma = *reinterpret_cast<const float2*>(
                &xf[((size_t)ba * J_JOINTS + j) * 16 + r * 4 + c2 * 2]);
        if (bb2 < B)
            mb = *reinterpret_cast<const float2*>(
                &xf[((size_t)bb2 * J_JOINTS + j) * 16 + r * 4 + c2 * 2]);

        double2 d;
        d.x = __longlong_as_double((long long)pack2(ma.x, mb.x));
        d.y = __longlong_as_double((long long)pack2(ma.y, mb.y));
        sM[bp][j][q] = d;
    }
    __syncthreads();

    const int t  = blockIdx.x * TPB + threadIdx.x;
    const int v0 = t * VPT;
    if (v0 >= V) return;

    // Vertex coords, splatted into f32x2. (V=100000 divisible by 4; clamp anyway.)
    u64 XX[VPT], YY[VPT], ZZ[VPT];
#pragma unroll
    for (int k = 0; k < VPT; k++) {
        int v = min(v0 + k, V - 1);
        float x = verts[v * 3 + 0];
        float y = verts[v * 3 + 1];
        float z = verts[v * 3 + 2];
        XX[k] = pack2(x, x);
        YY[k] = pack2(y, y);
        ZZ[k] = pack2(z, z);
    }

#pragma unroll 1
    for (int bp = 0; bp < BCHUNK / 2; bp++) {
        const int ba = b0 + 2 * bp;
        if (ba >= B) break;

        u64 A0[VPT], A1[VPT], A2[VPT];
#pragma unroll
        for (int k = 0; k < VPT; k++) { A0[k] = 0ULL; A1[k] = 0ULL; A2[k] = 0ULL; }

#pragma unroll 2
        for (int j = 0; j < J_JOINTS; j++) {
            double2 d0 = sM[bp][j][0];
            double2 d1 = sM[bp][j][1];
            double2 d2 = sM[bp][j][2];
            double2 d3 = sM[bp][j][3];
            double2 d4 = sM[bp][j][4];
            double2 d5 = sM[bp][j][5];
            u64 M0x = (u64)__double_as_longlong(d0.x);
            u64 M0y = (u64)__double_as_longlong(d0.y);
            u64 M0z = (u64)__double_as_longlong(d1.x);
            u64 M0w = (u64)__double_as_longlong(d1.y);
            u64 M1x = (u64)__double_as_longlong(d2.x);
            u64 M1y = (u64)__double_as_longlong(d2.y);
            u64 M1z = (u64)__double_as_longlong(d3.x);
            u64 M1w = (u64)__double_as_longlong(d3.y);
            u64 M2x = (u64)__double_as_longlong(d4.x);
            u64 M2y = (u64)__double_as_longlong(d4.y);
            u64 M2z = (u64)__double_as_longlong(d5.x);
            u64 M2w = (u64)__double_as_longlong(d5.y);

            // 4 consecutive vertices' weight for joint j: one LDG.128
            const float4 w4 = *reinterpret_cast<const float4*>(&g_wT[(size_t)j * V + v0]);
            u64 W[VPT];
            W[0] = pack2(w4.x, w4.x);
            W[1] = pack2(w4.y, w4.y);
            W[2] = pack2(w4.z, w4.z);
            W[3] = pack2(w4.w, w4.w);

#pragma unroll
            for (int k = 0; k < VPT; k++) {
                u64 r0 = ffma2(M0x, XX[k], ffma2(M0y, YY[k], ffma2(M0z, ZZ[k], M0w)));
                u64 r1 = ffma2(M1x, XX[k], ffma2(M1y, YY[k], ffma2(M1z, ZZ[k], M1w)));
                u64 r2 = ffma2(M2x, XX[k], ffma2(M2y, YY[k], ffma2(M2z, ZZ[k], M2w)));
                A0[k] = ffma2(W[k], r0, A0[k]);
                A1[k] = ffma2(W[k], r1, A1[k]);
                A2[k] = ffma2(W[k], r2, A2[k]);
            }
        }

        // Unpack and store: batch ba (lo halves) and ba+1 (hi halves).
        float a0[VPT], a1[VPT], a2[VPT];   // batch ba
        float c0[VPT], c1[VPT], c2[VPT];   // batch ba+1
#pragma unroll
        for (int k = 0; k < VPT; k++) {
            unpack2(A0[k], a0[k], c0[k]);
            unpack2(A1[k], a1[k], c1[k]);
            unpack2(A2[k], a2[k], c2[k]);
        }

        const int nv = min(VPT, V - v0);
        if (nv == VPT) {
            float4* oa = reinterpret_cast<float4*>(out + ((size_t)ba * V + v0) * 3);
            oa[0] = make_float4(a0[0], a1[0], a2[0], a0[1]);
            oa[1] = make_float4(a1[1], a2[1], a0[2], a1[2]);
            oa[2] = make_float4(a2[2], a0[3], a1[3], a2[3]);
            if (ba + 1 < B) {
                float4* ob = reinterpret_cast<float4*>(out + ((size_t)(ba + 1) * V + v0) * 3);
                ob[0] = make_float4(c0[0], c1[0], c2[0], c0[1]);
                ob[1] = make_float4(c1[1], c2[1], c0[2], c1[2]);
                ob[2] = make_float4(c2[2], c0[3], c1[3], c2[3]);
            }
        } else {
            for (int k = 0; k < nv; k++) {
                float* oa = out + ((size_t)ba * V + v0 + k) * 3;
                oa[0] = a0[k]; oa[1] = a1[k]; oa[2] = a2[k];
                if (ba + 1 < B) {
                    float* ob = out + ((size_t)(ba + 1) * V + v0 + k) * 3;
                    ob[0] = c0[k]; ob[1] = c1[k]; ob[2] = c2[k];
                }
            }
        }
    }
}

extern "C" void kernel_launch(void* const* d_in, const int* in_sizes, int n_in,
                              void* d_out, int out_size)
{
    const float* verts   = (const float*)d_in[0];
    const float* weights = (const float*)d_in[1];
    const float* xf      = (const float*)d_in[2];
    float*       out     = (float*)d_out;

    const int V = in_sizes[0] / 3;
    const int B = in_sizes[2] / (J_JOINTS * 16);

    // Pass 1: transpose weights into g_wT.
    {
        dim3 grid((V + TR_VERTS - 1) / TR_VERTS);
        transpose_w_kernel<<<grid, 256>>>(weights, V);
    }

    // Pass 2: skinning.
    {
        const int threads = (V + VPT - 1) / VPT;
        dim3 grid((threads + TPB - 1) / TPB, (B + BCHUNK - 1) / BCHUNK);
        skinning_kernel<<<grid, TPB>>>(verts, xf, out, V, B);
    }
}